// round 4
// baseline (speedup 1.0000x reference)
#include <cuda_runtime.h>
#include <math.h>

// ---------------- problem constants ----------------
#define TSEQ     1536
#define DMODEL   2880
#define HQ       64
#define HKV      8
#define HD       64
#define QKV_DIM  5120   // HD*(HQ+2*HKV)
#define ATT_DIM  4096   // HQ*HD
#define SM_SCALE 0.125f // 1/sqrt(64)

// ---------------- scratch (device globals; no runtime alloc) ----------------
__device__ float g_qkv[TSEQ * QKV_DIM];   // x@Wqkv + b, rope applied in place
__device__ float g_att[TSEQ * ATT_DIM];   // attention output, (t, head*64+d)
__device__ float2 g_cs[TSEQ * 32];        // (cos, sin) rope table

// ============================================================================
// fp32 GEMM with bias: C[M,N] = A[M,K] @ B[K,N] + bias[N]
// 128x128 block tile, BK=8, 256 threads, 8x8 per-thread microtile
// (split as 2x float4 in each dim for conflict-free shared reads)
// Requires: M % 128 == 0, K % 8 == 0. N remainder handled with guards.
// ============================================================================
#define BM 128
#define BN 128
#define BKK 8

__global__ __launch_bounds__(256) void sgemm_bias(
    const float* __restrict__ A, const float* __restrict__ B,
    const float* __restrict__ bias, float* __restrict__ C,
    int M, int N, int K)
{
    __shared__ float As[BKK][BM];
    __shared__ float Bs[BKK][BN];

    const int tid = threadIdx.x;
    const int m0  = blockIdx.y * BM;
    const int n0  = blockIdx.x * BN;
    const int tr  = tid >> 4;        // 0..15
    const int tc  = tid & 15;        // 0..15

    const int aRow = tid >> 1;              // 0..127
    const int aCol = (tid & 1) << 2;        // 0 or 4
    const int bRow = tid >> 5;              // 0..7
    const int bCol = (tid & 31) << 2;       // 0..124

    const bool fullN = (n0 + BN) <= N;

    float acc[8][8];
    #pragma unroll
    for (int i = 0; i < 8; i++)
        #pragma unroll
        for (int j = 0; j < 8; j++) acc[i][j] = 0.f;

    const float* Aptr = A + (size_t)(m0 + aRow) * K + aCol;

    for (int k0 = 0; k0 < K; k0 += BKK) {
        // A tile -> transposed in smem
        float4 av = *reinterpret_cast<const float4*>(Aptr + k0);
        As[aCol + 0][aRow] = av.x;
        As[aCol + 1][aRow] = av.y;
        As[aCol + 2][aRow] = av.z;
        As[aCol + 3][aRow] = av.w;
        // B tile
        if (fullN) {
            float4 bv = *reinterpret_cast<const float4*>(
                &B[(size_t)(k0 + bRow) * N + n0 + bCol]);
            *reinterpret_cast<float4*>(&Bs[bRow][bCol]) = bv;
        } else {
            #pragma unroll
            for (int i = 0; i < 4; i++) {
                int col = n0 + bCol + i;
                Bs[bRow][bCol + i] = (col < N) ? B[(size_t)(k0 + bRow) * N + col] : 0.f;
            }
        }
        __syncthreads();

        #pragma unroll
        for (int kk = 0; kk < BKK; ++kk) {
            float4 a0 = *reinterpret_cast<const float4*>(&As[kk][tr * 4]);
            float4 a1 = *reinterpret_cast<const float4*>(&As[kk][64 + tr * 4]);
            float4 b0 = *reinterpret_cast<const float4*>(&Bs[kk][tc * 4]);
            float4 b1 = *reinterpret_cast<const float4*>(&Bs[kk][64 + tc * 4]);
            float rm[8] = {a0.x, a0.y, a0.z, a0.w, a1.x, a1.y, a1.z, a1.w};
            float rn[8] = {b0.x, b0.y, b0.z, b0.w, b1.x, b1.y, b1.z, b1.w};
            #pragma unroll
            for (int i = 0; i < 8; i++)
                #pragma unroll
                for (int j = 0; j < 8; j++)
                    acc[i][j] = fmaf(rm[i], rn[j], acc[i][j]);
        }
        __syncthreads();
    }

    #pragma unroll
    for (int i = 0; i < 8; i++) {
        int row = m0 + ((i < 4) ? (tr * 4 + i) : (64 + tr * 4 + (i - 4)));
        #pragma unroll
        for (int j = 0; j < 8; j++) {
            int col = n0 + ((j < 4) ? (tc * 4 + j) : (64 + tc * 4 + (j - 4)));
            if (col < N)
                C[(size_t)row * N + col] = acc[i][j] + bias[col];
        }
    }
}

// ============================================================================
// RoPE: YaRN (NTK-by-parts) table.  Mirrors the reference float32 dataflow:
// inv_freq rounded to float32, angle = float32(t) * inv_freq (float32 mult),
// then cos/sin evaluated precisely on that float32 angle.
// ============================================================================
__global__ void rope_table_kernel()
{
    int idx = blockIdx.x * blockDim.x + threadIdx.x;
    if (idx >= TSEQ * 32) return;
    int t = idx >> 5;
    int i = idx & 31;

    const double base  = 150000.0;
    const double twopi = 6.283185307179586476925286766559;
    double freq = pow(base, (double)(2 * i) / 64.0);
    double conc = 0.1 * log(32.0) + 1.0;
    double lb   = log(base);
    double low  = 32.0 * log(1024.0 / (32.0 * twopi)) / lb;
    double high = 32.0 * log(1024.0 / twopi) / lb;
    double r = ((double)i - low) / (high - low);
    r = fmin(1.0, fmax(0.0, r));
    double inv = r / (32.0 * freq) + (1.0 - r) / freq;

    float invf = (float)inv;             // match np float32 inv_freq
    float angf = (float)t * invf;        // match np float32 outer product
    double ang = (double)angf;
    g_cs[idx] = make_float2((float)(cos(ang) * conc), (float)(sin(ang) * conc));
}

// Apply rope in-place to q (rope-heads 0..63) and k (rope-heads 64..71).
__global__ void rope_apply_kernel()
{
    int idx = blockIdx.x * blockDim.x + threadIdx.x;
    if (idx >= TSEQ * 72 * 32) return;
    int i = idx & 31;
    int h = (idx >> 5) % 72;
    int t = idx / (72 * 32);

    float2 cs = g_cs[t * 32 + i];
    float* p = &g_qkv[(size_t)t * QKV_DIM + h * 64];
    float x1 = p[i];
    float x2 = p[i + 32];
    p[i]      = x1 * cs.x - x2 * cs.y;
    p[i + 32] = x2 * cs.x + x1 * cs.y;
}

// ============================================================================
// Sliding-window GQA attention with sink.
// Block = (64-query tile, kv head).  K/V window of 192 rows staged in dynamic
// smem (stride 68 floats: float4 score reads & float2 PV reads conflict-free).
// Warp = query head (8 warps), lane = key (score phase) / 2 dims (PV phase).
// ============================================================================
#define QT    64
#define KEYS  192   // 191 used (t0-127 .. t0+63), row 191 zero-filled
#define KSTR  68
#define ATTN_SMEM (2 * KEYS * KSTR * 4)

__global__ __launch_bounds__(256) void attn_kernel(const float* __restrict__ sinks)
{
    extern __shared__ float smem[];
    float* Ks = smem;
    float* Vs = smem + KEYS * KSTR;
    __shared__ float Qbuf[8][64];

    const int t0   = blockIdx.x * QT;
    const int hkv  = blockIdx.y;
    const int tid  = threadIdx.x;
    const int warp = tid >> 5;
    const int lane = tid & 31;

    // stage K/V window (zero-fill out-of-range rows so 0*w never makes NaN)
    for (int r = tid; r < KEYS * 16; r += 256) {
        int kk = r >> 4;
        int c4 = (r & 15) << 2;
        int ka = t0 - 127 + kk;
        float4 kv = make_float4(0.f, 0.f, 0.f, 0.f);
        float4 vv = kv;
        if (ka >= 0 && ka < TSEQ) {
            kv = *reinterpret_cast<const float4*>(
                &g_qkv[(size_t)ka * QKV_DIM + 4096 + hkv * 64 + c4]);
            vv = *reinterpret_cast<const float4*>(
                &g_qkv[(size_t)ka * QKV_DIM + 4608 + hkv * 64 + c4]);
        }
        *reinterpret_cast<float4*>(&Ks[kk * KSTR + c4]) = kv;
        *reinterpret_cast<float4*>(&Vs[kk * KSTR + c4]) = vv;
    }
    __syncthreads();

    const int   hg   = hkv * 8 + warp;
    const float sink = sinks[hg];
    float2* qb2 = reinterpret_cast<float2*>(Qbuf[warp]);

    for (int qr = 0; qr < QT; ++qr) {
        const int qa = t0 + qr;
        __syncwarp();
        qb2[lane] = *reinterpret_cast<const float2*>(
            &g_qkv[(size_t)qa * QKV_DIM + hg * 64 + 2 * lane]);
        __syncwarp();

        // scores: lane owns keys lane, lane+32, ...
        float e[6];
        float mloc = -1e30f;
        #pragma unroll
        for (int c = 0; c < 6; ++c) {
            int kk = c * 32 + lane;
            // key abs index ka = t0-127+kk; valid: qr <= kk <= qr+127 and ka >= 0
            bool valid = (kk >= qr) && (kk <= qr + 127) && (t0 - 127 + kk >= 0);
            float s = -1e30f;
            if (valid) {
                const float4* krow = reinterpret_cast<const float4*>(&Ks[kk * KSTR]);
                const float4* qrow = reinterpret_cast<const float4*>(Qbuf[warp]);
                float acc = 0.f;
                #pragma unroll
                for (int d = 0; d < 16; ++d) {
                    float4 k4 = krow[d];
                    float4 q4 = qrow[d];
                    acc = fmaf(k4.x, q4.x, acc);
                    acc = fmaf(k4.y, q4.y, acc);
                    acc = fmaf(k4.z, q4.z, acc);
                    acc = fmaf(k4.w, q4.w, acc);
                }
                s = acc * SM_SCALE;
            }
            e[c] = s;
            mloc = fmaxf(mloc, s);
        }
        #pragma unroll
        for (int off = 16; off; off >>= 1)
            mloc = fmaxf(mloc, __shfl_xor_sync(0xffffffffu, mloc, off));

        float sum = 0.f;
        #pragma unroll
        for (int c = 0; c < 6; ++c) {
            float ex = (e[c] > -1e29f) ? expf(e[c] - mloc) : 0.f;
            e[c] = ex;
            sum += ex;
        }
        #pragma unroll
        for (int off = 16; off; off >>= 1)
            sum += __shfl_xor_sync(0xffffffffu, sum, off);
        const float rden = 1.f / (sum + expf(sink - mloc));

        // PV: lane owns dims 2*lane, 2*lane+1
        float ox = 0.f, oy = 0.f;
        #pragma unroll
        for (int c = 0; c < 6; ++c) {
            float wc = e[c] * rden;
            if (!__any_sync(0xffffffffu, wc > 0.f)) continue;
            #pragma unroll
            for (int l = 0; l < 32; ++l) {
                float w = __shfl_sync(0xffffffffu, wc, l);
                const float2 v2 = *reinterpret_cast<const float2*>(
                    &Vs[(c * 32 + l) * KSTR + 2 * lane]);
                ox = fmaf(w, v2.x, ox);
                oy = fmaf(w, v2.y, oy);
            }
        }
        *reinterpret_cast<float2*>(
            &g_att[(size_t)qa * ATT_DIM + hg * 64 + 2 * lane]) = make_float2(ox, oy);
    }
}

// ============================================================================
// launch
// ============================================================================
extern "C" void kernel_launch(void* const* d_in, const int* in_sizes, int n_in,
                              void* d_out, int out_size)
{
    (void)in_sizes; (void)n_in; (void)out_size;
    const float* x     = (const float*)d_in[0];
    const float* Wqkv  = (const float*)d_in[1];
    const float* bqkv  = (const float*)d_in[2];
    const float* Wout  = (const float*)d_in[3];
    const float* bout  = (const float*)d_in[4];
    const float* sinks = (const float*)d_in[5];
    float* out = (float*)d_out;

    float *qkv_ptr = nullptr, *att_ptr = nullptr;
    cudaGetSymbolAddress((void**)&qkv_ptr, g_qkv);
    cudaGetSymbolAddress((void**)&att_ptr, g_att);

    cudaFuncSetAttribute(attn_kernel,
                         cudaFuncAttributeMaxDynamicSharedMemorySize, ATTN_SMEM);

    // 1) qkv = x @ Wqkv + bqkv            (1536x2880 @ 2880x5120)
    sgemm_bias<<<dim3(QKV_DIM / BN, TSEQ / BM), 256>>>(
        x, Wqkv, bqkv, qkv_ptr, TSEQ, QKV_DIM, DMODEL);

    // 2) rope tables + in-place rope on q,k
    rope_table_kernel<<<(TSEQ * 32 + 255) / 256, 256>>>();
    rope_apply_kernel<<<(TSEQ * 72 * 32 + 255) / 256, 256>>>();

    // 3) sliding-window GQA attention with sink
    attn_kernel<<<dim3(TSEQ / QT, HKV), 256, ATTN_SMEM>>>(sinks);

    // 4) out = att @ Wout + bout          (1536x4096 @ 4096x2880)
    sgemm_bias<<<dim3((DMODEL + BN - 1) / BN, TSEQ / BM), 256>>>(
        att_ptr, Wout, bout, out, TSEQ, DMODEL, ATT_DIM);
}

// round 8
// speedup vs baseline: 2.1514x; 2.1514x over previous
#include <cuda_runtime.h>
#include <cuda_bf16.h>
#include <math.h>

// ---------------- problem constants ----------------
#define TSEQ     1536
#define DMODEL   2880
#define HQ       64
#define HKV      8
#define HD       64
#define QKV_DIM  5120   // HD*(HQ+2*HKV)
#define ATT_DIM  4096   // HQ*HD
#define SM_SCALE 0.125f // 1/sqrt(64)

// ---------------- scratch (device globals; no runtime alloc) ----------------
__device__ float g_qkv[TSEQ * QKV_DIM];   // x@Wqkv + b, rope applied in place
__device__ float g_att[TSEQ * ATT_DIM];   // attention output, (t, head*64+d)
__device__ float2 g_cs[TSEQ * 32];        // (cos, sin) rope table

// hi/lo bf16 split buffers for tensor-core GEMMs
__device__ __align__(16) __nv_bfloat16 g_xh[TSEQ * DMODEL];
__device__ __align__(16) __nv_bfloat16 g_xl[TSEQ * DMODEL];
__device__ __align__(16) __nv_bfloat16 g_wqh[DMODEL * QKV_DIM];
__device__ __align__(16) __nv_bfloat16 g_wql[DMODEL * QKV_DIM];
__device__ __align__(16) __nv_bfloat16 g_woh[ATT_DIM * DMODEL];
__device__ __align__(16) __nv_bfloat16 g_wol[ATT_DIM * DMODEL];
__device__ __align__(16) __nv_bfloat16 g_ah[TSEQ * ATT_DIM];
__device__ __align__(16) __nv_bfloat16 g_al[TSEQ * ATT_DIM];

// ============================================================================
// fp32 -> (hi, lo) bf16 split, vectorized
// ============================================================================
__global__ void cvt_hilo(const float* __restrict__ s, __nv_bfloat16* __restrict__ h,
                         __nv_bfloat16* __restrict__ l, int n4)
{
    int i = blockIdx.x * blockDim.x + threadIdx.x;
    if (i >= n4) return;
    float4 v = reinterpret_cast<const float4*>(s)[i];
    __nv_bfloat16 h0 = __float2bfloat16(v.x), h1 = __float2bfloat16(v.y);
    __nv_bfloat16 h2 = __float2bfloat16(v.z), h3 = __float2bfloat16(v.w);
    float r0 = v.x - __bfloat162float(h0), r1 = v.y - __bfloat162float(h1);
    float r2 = v.z - __bfloat162float(h2), r3 = v.w - __bfloat162float(h3);
    __nv_bfloat162* hp = reinterpret_cast<__nv_bfloat162*>(h + 4 * (size_t)i);
    hp[0] = __halves2bfloat162(h0, h1);
    hp[1] = __halves2bfloat162(h2, h3);
    __nv_bfloat162* lp = reinterpret_cast<__nv_bfloat162*>(l + 4 * (size_t)i);
    lp[0] = __halves2bfloat162(__float2bfloat16(r0), __float2bfloat16(r1));
    lp[1] = __halves2bfloat162(__float2bfloat16(r2), __float2bfloat16(r3));
}

// ============================================================================
// Tensor-core GEMM (bf16x3 split fp32 emulation):
//   C[M,N] = A[M,K] @ B[K,N] + bias  with A,B given as hi/lo bf16 pairs.
// 128x128 tile, BK=16, 256 threads (8 warps = 2x4), warp tile 64x32.
// mma.sync.m16n8k16 f32.bf16 accumulate; 3 passes: Ah*Bh + Ah*Bl + Al*Bh.
// Requires M%128==0, K%16==0, N%8==0 (tail tiles in N handled by guards).
// ============================================================================
#define GBK  16
#define ASTR 24    // A smem row stride in bf16 (48B: conflict-free ldmatrix)
#define BSTR 136   // B smem row stride in bf16 (272B: conflict-free ldmatrix)

__device__ __forceinline__ unsigned sptr(const void* p)
{
    return (unsigned)__cvta_generic_to_shared(p);
}

__device__ __forceinline__ void ldsm_x4(unsigned* r, unsigned addr)
{
    asm volatile("ldmatrix.sync.aligned.m8n8.x4.shared.b16 {%0,%1,%2,%3}, [%4];"
                 : "=r"(r[0]), "=r"(r[1]), "=r"(r[2]), "=r"(r[3]) : "r"(addr));
}

__device__ __forceinline__ void ldsm_x2t(unsigned* r, unsigned addr)
{
    asm volatile("ldmatrix.sync.aligned.m8n8.x2.trans.shared.b16 {%0,%1}, [%2];"
                 : "=r"(r[0]), "=r"(r[1]) : "r"(addr));
}

__device__ __forceinline__ void mma16816(float* c, const unsigned* a, const unsigned* b)
{
    asm volatile("mma.sync.aligned.m16n8k16.row.col.f32.bf16.bf16.f32 "
                 "{%0,%1,%2,%3}, {%4,%5,%6,%7}, {%8,%9}, {%0,%1,%2,%3};"
                 : "+f"(c[0]), "+f"(c[1]), "+f"(c[2]), "+f"(c[3])
                 : "r"(a[0]), "r"(a[1]), "r"(a[2]), "r"(a[3]), "r"(b[0]), "r"(b[1]));
}

__global__ __launch_bounds__(256) void gemm_bf16x3(
    const __nv_bfloat16* __restrict__ Agh, const __nv_bfloat16* __restrict__ Agl,
    const __nv_bfloat16* __restrict__ Bgh, const __nv_bfloat16* __restrict__ Bgl,
    const float* __restrict__ bias, float* __restrict__ C, int N, int K)
{
    __shared__ __align__(16) __nv_bfloat16 sA[2][2][128 * ASTR];
    __shared__ __align__(16) __nv_bfloat16 sB[2][2][GBK * BSTR];

    const int tid  = threadIdx.x;
    const int warp = tid >> 5, lane = tid & 31;
    const int wm   = warp >> 2, wn = warp & 3;
    const int m0   = blockIdx.y * 128, n0 = blockIdx.x * 128;

    // global->smem loader mapping (uint4 = 8 bf16 per thread per array)
    const int arow = tid >> 1, ak = (tid & 1) * 8;   // A: 128 rows x 16 k
    const int brow = tid >> 4, bc = (tid & 15) * 8;  // B: 16 rows x 128 n
    const bool bok = (n0 + bc) < N;

    const __nv_bfloat16* gAh = Agh + (size_t)(m0 + arow) * K + ak;
    const __nv_bfloat16* gAl = Agl + (size_t)(m0 + arow) * K + ak;
    const __nv_bfloat16* gBh = Bgh + (size_t)brow * N + n0 + bc;
    const __nv_bfloat16* gBl = Bgl + (size_t)brow * N + n0 + bc;

    float acc[4][4][4];
    #pragma unroll
    for (int i = 0; i < 4; i++)
        #pragma unroll
        for (int j = 0; j < 4; j++)
            #pragma unroll
            for (int k = 0; k < 4; k++) acc[i][j][k] = 0.f;

    const uint4 z = make_uint4(0u, 0u, 0u, 0u);
    const int nk = K / GBK;

    // preload chunk 0
    uint4 rAh = *(const uint4*)gAh;
    uint4 rAl = *(const uint4*)gAl;
    uint4 rBh = bok ? *(const uint4*)gBh : z;
    uint4 rBl = bok ? *(const uint4*)gBl : z;
    *(uint4*)&sA[0][0][arow * ASTR + ak] = rAh;
    *(uint4*)&sA[0][1][arow * ASTR + ak] = rAl;
    *(uint4*)&sB[0][0][brow * BSTR + bc] = rBh;
    *(uint4*)&sB[0][1][brow * BSTR + bc] = rBl;
    __syncthreads();

    const int r16 = lane & 15;
    const int ks  = (lane >> 4) * 8;

    for (int kc = 0; kc < nk; ++kc) {
        const int s = kc & 1;
        if (kc + 1 < nk) {
            const size_t go = (size_t)(kc + 1) * GBK;
            rAh = *(const uint4*)(gAh + go);
            rAl = *(const uint4*)(gAl + go);
            rBh = bok ? *(const uint4*)(gBh + go * N) : z;
            rBl = bok ? *(const uint4*)(gBl + go * N) : z;
        }

        // B fragments (k16 x n8) for the warp's 4 n-tiles, hi and lo
        unsigned bh[4][2], bl[4][2];
        #pragma unroll
        for (int nt = 0; nt < 4; ++nt) {
            const int bo = r16 * BSTR + wn * 32 + nt * 8;
            ldsm_x2t(bh[nt], sptr(&sB[s][0][bo]));
            ldsm_x2t(bl[nt], sptr(&sB[s][1][bo]));
        }
        // A fragments per m-tile, then 12 mma
        #pragma unroll
        for (int mt = 0; mt < 4; ++mt) {
            unsigned ah[4], al[4];
            const int ao = (wm * 64 + mt * 16 + r16) * ASTR + ks;
            ldsm_x4(ah, sptr(&sA[s][0][ao]));
            ldsm_x4(al, sptr(&sA[s][1][ao]));
            #pragma unroll
            for (int nt = 0; nt < 4; ++nt) {
                mma16816(acc[mt][nt], ah, bh[nt]);
                mma16816(acc[mt][nt], ah, bl[nt]);
                mma16816(acc[mt][nt], al, bh[nt]);
            }
        }

        if (kc + 1 < nk) {
            const int s1 = s ^ 1;
            *(uint4*)&sA[s1][0][arow * ASTR + ak] = rAh;
            *(uint4*)&sA[s1][1][arow * ASTR + ak] = rAl;
            *(uint4*)&sB[s1][0][brow * BSTR + bc] = rBh;
            *(uint4*)&sB[s1][1][brow * BSTR + bc] = rBl;
        }
        __syncthreads();
    }

    // epilogue: C fragment -> (row=l>>2, col=2*(l&3)) pairs, + bias
    const int er = lane >> 2;
    const int ec = (lane & 3) * 2;
    #pragma unroll
    for (int mt = 0; mt < 4; ++mt) {
        const int row = m0 + wm * 64 + mt * 16 + er;
        #pragma unroll
        for (int nt = 0; nt < 4; ++nt) {
            const int col = n0 + wn * 32 + nt * 8 + ec;
            if (col < N) {
                const float b0 = bias[col], b1 = bias[col + 1];
                *(float2*)&C[(size_t)row * N + col] =
                    make_float2(acc[mt][nt][0] + b0, acc[mt][nt][1] + b1);
                *(float2*)&C[(size_t)(row + 8) * N + col] =
                    make_float2(acc[mt][nt][2] + b0, acc[mt][nt][3] + b1);
            }
        }
    }
}

// ============================================================================
// RoPE: YaRN (NTK-by-parts) table, mirrors reference float32 dataflow.
// ============================================================================
__global__ void rope_table_kernel()
{
    int idx = blockIdx.x * blockDim.x + threadIdx.x;
    if (idx >= TSEQ * 32) return;
    int t = idx >> 5;
    int i = idx & 31;

    const double base  = 150000.0;
    const double twopi = 6.283185307179586476925286766559;
    double freq = pow(base, (double)(2 * i) / 64.0);
    double conc = 0.1 * log(32.0) + 1.0;
    double lb   = log(base);
    double low  = 32.0 * log(1024.0 / (32.0 * twopi)) / lb;
    double high = 32.0 * log(1024.0 / twopi) / lb;
    double r = ((double)i - low) / (high - low);
    r = fmin(1.0, fmax(0.0, r));
    double inv = r / (32.0 * freq) + (1.0 - r) / freq;

    float invf = (float)inv;
    float angf = (float)t * invf;
    double ang = (double)angf;
    g_cs[idx] = make_float2((float)(cos(ang) * conc), (float)(sin(ang) * conc));
}

__global__ void rope_apply_kernel()
{
    int idx = blockIdx.x * blockDim.x + threadIdx.x;
    if (idx >= TSEQ * 72 * 32) return;
    int i = idx & 31;
    int h = (idx >> 5) % 72;
    int t = idx / (72 * 32);

    float2 cs = g_cs[t * 32 + i];
    float* p = &g_qkv[(size_t)t * QKV_DIM + h * 64];
    float x1 = p[i];
    float x2 = p[i + 32];
    p[i]      = x1 * cs.x - x2 * cs.y;
    p[i + 32] = x2 * cs.x + x1 * cs.y;
}

// ============================================================================
// Sliding-window GQA attention with sink.  QT=32 queries per block (better
// wave balance: 384 blocks), KEYS=160 window rows staged in smem.
// ============================================================================
#define QT    32
#define KEYS  160   // rows t0-127 .. t0+31; row 159 zero-filled
#define KSTR  68
#define ATTN_SMEM (2 * KEYS * KSTR * 4)

__global__ __launch_bounds__(256) void attn_kernel(const float* __restrict__ sinks)
{
    extern __shared__ float smem[];
    float* Ks = smem;
    float* Vs = smem + KEYS * KSTR;
    __shared__ float Qbuf[8][64];

    const int t0   = blockIdx.x * QT;
    const int hkv  = blockIdx.y;
    const int tid  = threadIdx.x;
    const int warp = tid >> 5;
    const int lane = tid & 31;

    for (int r = tid; r < KEYS * 16; r += 256) {
        int kk = r >> 4;
        int c4 = (r & 15) << 2;
        int ka = t0 - 127 + kk;
        float4 kv = make_float4(0.f, 0.f, 0.f, 0.f);
        float4 vv = kv;
        if (ka >= 0 && ka < TSEQ) {
            kv = *reinterpret_cast<const float4*>(
                &g_qkv[(size_t)ka * QKV_DIM + 4096 + hkv * 64 + c4]);
            vv = *reinterpret_cast<const float4*>(
                &g_qkv[(size_t)ka * QKV_DIM + 4608 + hkv * 64 + c4]);
        }
        *reinterpret_cast<float4*>(&Ks[kk * KSTR + c4]) = kv;
        *reinterpret_cast<float4*>(&Vs[kk * KSTR + c4]) = vv;
    }
    __syncthreads();

    const int   hg   = hkv * 8 + warp;
    const float sink = sinks[hg];
    float2* qb2 = reinterpret_cast<float2*>(Qbuf[warp]);

    for (int qr = 0; qr < QT; ++qr) {
        const int qa = t0 + qr;
        __syncwarp();
        qb2[lane] = *reinterpret_cast<const float2*>(
            &g_qkv[(size_t)qa * QKV_DIM + hg * 64 + 2 * lane]);
        __syncwarp();

        float e[5];
        float mloc = -1e30f;
        #pragma unroll
        for (int c = 0; c < 5; ++c) {
            int kk = c * 32 + lane;
            bool valid = (kk >= qr) && (kk <= qr + 127) && (t0 - 127 + kk >= 0);
            float s = -1e30f;
            if (valid) {
                const float4* krow = reinterpret_cast<const float4*>(&Ks[kk * KSTR]);
                const float4* qrow = reinterpret_cast<const float4*>(Qbuf[warp]);
                float acc = 0.f;
                #pragma unroll
                for (int d = 0; d < 16; ++d) {
                    float4 k4 = krow[d];
                    float4 q4 = qrow[d];
                    acc = fmaf(k4.x, q4.x, acc);
                    acc = fmaf(k4.y, q4.y, acc);
                    acc = fmaf(k4.z, q4.z, acc);
                    acc = fmaf(k4.w, q4.w, acc);
                }
                s = acc * SM_SCALE;
            }
            e[c] = s;
            mloc = fmaxf(mloc, s);
        }
        #pragma unroll
        for (int off = 16; off; off >>= 1)
            mloc = fmaxf(mloc, __shfl_xor_sync(0xffffffffu, mloc, off));

        float sum = 0.f;
        #pragma unroll
        for (int c = 0; c < 5; ++c) {
            float ex = (e[c] > -1e29f) ? expf(e[c] - mloc) : 0.f;
            e[c] = ex;
            sum += ex;
        }
        #pragma unroll
        for (int off = 16; off; off >>= 1)
            sum += __shfl_xor_sync(0xffffffffu, sum, off);
        const float rden = 1.f / (sum + expf(sink - mloc));

        float ox = 0.f, oy = 0.f;
        #pragma unroll
        for (int c = 0; c < 5; ++c) {
            float wc = e[c] * rden;
            if (!__any_sync(0xffffffffu, wc > 0.f)) continue;
            #pragma unroll
            for (int l = 0; l < 32; ++l) {
                float w = __shfl_sync(0xffffffffu, wc, l);
                const float2 v2 = *reinterpret_cast<const float2*>(
                    &Vs[(c * 32 + l) * KSTR + 2 * lane]);
                ox = fmaf(w, v2.x, ox);
                oy = fmaf(w, v2.y, oy);
            }
        }
        *reinterpret_cast<float2*>(
            &g_att[(size_t)qa * ATT_DIM + hg * 64 + 2 * lane]) = make_float2(ox, oy);
    }
}

// ============================================================================
// launch
// ============================================================================
extern "C" void kernel_launch(void* const* d_in, const int* in_sizes, int n_in,
                              void* d_out, int out_size)
{
    (void)in_sizes; (void)n_in; (void)out_size;
    const float* x     = (const float*)d_in[0];
    const float* Wqkv  = (const float*)d_in[1];
    const float* bqkv  = (const float*)d_in[2];
    const float* Wout  = (const float*)d_in[3];
    const float* bout  = (const float*)d_in[4];
    const float* sinks = (const float*)d_in[5];
    float* out = (float*)d_out;

    float *qkv_ptr = nullptr, *att_ptr = nullptr;
    __nv_bfloat16 *xh, *xl, *wqh, *wql, *woh, *wol, *ah, *al;
    cudaGetSymbolAddress((void**)&qkv_ptr, g_qkv);
    cudaGetSymbolAddress((void**)&att_ptr, g_att);
    cudaGetSymbolAddress((void**)&xh,  g_xh);
    cudaGetSymbolAddress((void**)&xl,  g_xl);
    cudaGetSymbolAddress((void**)&wqh, g_wqh);
    cudaGetSymbolAddress((void**)&wql, g_wql);
    cudaGetSymbolAddress((void**)&woh, g_woh);
    cudaGetSymbolAddress((void**)&wol, g_wol);
    cudaGetSymbolAddress((void**)&ah,  g_ah);
    cudaGetSymbolAddress((void**)&al,  g_al);

    cudaFuncSetAttribute(attn_kernel,
                         cudaFuncAttributeMaxDynamicSharedMemorySize, ATTN_SMEM);

    // 0) hi/lo bf16 splits of x and the weights
    {
        int n4;
        n4 = TSEQ * DMODEL / 4;
        cvt_hilo<<<(n4 + 255) / 256, 256>>>(x, xh, xl, n4);
        n4 = DMODEL * QKV_DIM / 4;
        cvt_hilo<<<(n4 + 255) / 256, 256>>>(Wqkv, wqh, wql, n4);
        n4 = ATT_DIM * DMODEL / 4;
        cvt_hilo<<<(n4 + 255) / 256, 256>>>(Wout, woh, wol, n4);
    }

    // 1) qkv = x @ Wqkv + bqkv   (1536x2880 @ 2880x5120, tensor cores)
    gemm_bf16x3<<<dim3(QKV_DIM / 128, TSEQ / 128), 256>>>(
        xh, xl, wqh, wql, bqkv, qkv_ptr, QKV_DIM, DMODEL);

    // 2) rope
    rope_table_kernel<<<(TSEQ * 32 + 255) / 256, 256>>>();
    rope_apply_kernel<<<(TSEQ * 72 * 32 + 255) / 256, 256>>>();

    // 3) sliding-window GQA attention with sink
    attn_kernel<<<dim3(TSEQ / QT, HKV), 256, ATTN_SMEM>>>(sinks);

    // 4) split att, then out = att @ Wout + bout (1536x4096 @ 4096x2880)
    {
        int n4 = TSEQ * ATT_DIM / 4;
        cvt_hilo<<<(n4 + 255) / 256, 256>>>(att_ptr, ah, al, n4);
    }
    gemm_bf16x3<<<dim3((DMODEL + 127) / 128, TSEQ / 128), 256>>>(
        ah, al, woh, wol, bout, out, DMODEL, ATT_DIM);
}